// round 5
// baseline (speedup 1.0000x reference)
#include <cuda_runtime.h>
#include <cuda_bf16.h>
#include <math.h>
#include <stdint.h>

#define BB 16
#define KMAX 4096
#define DK 512
#define AA 512
#define DV 512
#define MM (BB*KMAX)   // 65536

// ---------------- scratch (device globals) ----------------------------------
__device__ float g_vw[AA];                       // weight-normed v vector
__device__ float g_qb[BB][AA];                   // q projection + wk bias
__device__ float g_e[MM];                        // e_mono
// wk in bf16, mma-B-fragment order: [nt(8)][kt(32)][t(8)][lane(32)][j(2)] b32
__device__ __align__(16) uint32_t g_wkbf[AA * DK / 2];

// ==================== small helpers =========================================
__device__ __forceinline__ uint32_t smem_u32(const void* p) {
    uint32_t a;
    asm("{ .reg .u64 t; cvta.to.shared.u64 t, %1; cvt.u32.u64 %0, t; }"
        : "=r"(a) : "l"(p));
    return a;
}

__device__ __forceinline__ uint32_t pack_bf16x2(float lo, float hi) {
    __nv_bfloat162 h = __floats2bfloat162_rn(lo, hi);   // .x = lo (low half)
    return *reinterpret_cast<uint32_t*>(&h);
}

__device__ __forceinline__ void cp_async16(uint32_t dst, const void* src) {
    asm volatile("cp.async.cg.shared.global [%0], [%1], 16;"
                 :: "r"(dst), "l"(src) : "memory");
}
#define CP_COMMIT()  asm volatile("cp.async.commit_group;" ::: "memory")
#define CP_WAIT(N)   asm volatile("cp.async.wait_group %0;" :: "n"(N) : "memory")

__device__ __forceinline__ void mma16816(float& d0, float& d1, float& d2, float& d3,
                                         uint32_t a0, uint32_t a1, uint32_t a2, uint32_t a3,
                                         uint32_t b0, uint32_t b1) {
    asm volatile(
        "mma.sync.aligned.m16n8k16.row.col.f32.bf16.bf16.f32 "
        "{%0,%1,%2,%3}, {%4,%5,%6,%7}, {%8,%9}, {%0,%1,%2,%3};"
        : "+f"(d0), "+f"(d1), "+f"(d2), "+f"(d3)
        : "r"(a0), "r"(a1), "r"(a2), "r"(a3), "r"(b0), "r"(b1));
}

// ==================== kernel A1: v_w ========================================
__global__ void vw_kernel(const float* __restrict__ vv, const float* __restrict__ vg) {
    __shared__ float sh[AA];
    int t = threadIdx.x;
    float x = vv[t];
    sh[t] = x * x;
    __syncthreads();
    for (int s = 256; s > 0; s >>= 1) {
        if (t < s) sh[t] += sh[t + s];
        __syncthreads();
    }
    float nrm = sqrtf(sh[0]);
    g_vw[t] = vg[0] * x / nrm;
}

// ==================== kernel A2: qb[b][a] ===================================
__global__ void qproj_kernel(const float* __restrict__ query,
                             const float* __restrict__ wq,
                             const float* __restrict__ wkb) {
    int gw   = (blockIdx.x * blockDim.x + threadIdx.x) >> 5;
    int lane = threadIdx.x & 31;
    if (gw >= BB * AA) return;
    int b = gw >> 9;
    int a = gw & 511;
    const float* qp = query + (size_t)b * DK;
    const float* wp = wq + (size_t)a * DK;
    float s = 0.f;
    #pragma unroll 4
    for (int d = lane; d < DK; d += 32) s += qp[d] * wp[d];
    #pragma unroll
    for (int o = 16; o > 0; o >>= 1) s += __shfl_down_sync(0xffffffffu, s, o);
    if (lane == 0) g_qb[b][a] = s + wkb[a];
}

// ==================== kernel A3: wk -> bf16 fragment order ==================
// B frag (m16n8k16 col): b0 halves k=(lane%4)*2+{0,1}, n=lane/4 ; b1 same k+8.
__global__ __launch_bounds__(256) void wkconv_kernel(const float* __restrict__ wk) {
    int idx = blockIdx.x * 256 + threadIdx.x;      // over b32 pairs: 131072
    int a  = idx >> 8;                             // 0..511  (n)
    int dp = idx & 255;                            // d pair
    int d  = dp * 2;
    float2 f = *(const float2*)(wk + (size_t)a * DK + d);
    int nt = a >> 6;
    int t  = (a >> 3) & 7;
    int lr = a & 7;
    int kt = d >> 4;
    int lane = lr * 4 + ((d & 7) >> 1);
    int j = (d & 15) >> 3;
    uint32_t off = ((((nt * 32 + kt) * 8 + t) * 32) + lane) * 2 + j;
    g_wkbf[off] = pack_bf16x2(f.x, f.y);
}

// ==================== kernel B: mma.sync bf16 GEMM + fused epilogue =========
// CTA: 128 rows x 512 cols x K=512. A bf16 in smem (fragment order),
// B streamed via cp.async double-buffered 8KB chunks (64 chunks).
// smem layout (bytes):
#define SOFF_QB   0u
#define SOFF_VW   2048u
#define SOFF_A    4096u                  // 8 mt * 32 kt * 32 lane * 16B = 131072
#define SOFF_B    (4096u + 131072u)      // 2 * 8192
#define SMEM_GEMM (SOFF_B + 2u * 8192u)  // 151552

__global__ __launch_bounds__(256, 1) void gemm_mma_kernel(
        const float* __restrict__ key) {
    extern __shared__ char smem[];
    const uint32_t sb = smem_u32(smem);
    float* sqb = (float*)(smem + SOFF_QB);
    float* svw = (float*)(smem + SOFF_VW);
    uint4* sA  = (uint4*)(smem + SOFF_A);

    const int tid  = threadIdx.x;
    const int w    = tid >> 5;
    const int lane = tid & 31;
    const int row0 = blockIdx.x * 128;
    const int b    = blockIdx.x >> 5;

    // prefetch B chunk 0 early (contiguous 8KB from g_wkbf)
    {
        const char* src = (const char*)g_wkbf + (size_t)tid * 16;
        cp_async16(sb + SOFF_B + tid * 16, src);
        cp_async16(sb + SOFF_B + tid * 16 + 4096u, src + 4096);
        CP_COMMIT();
    }

    // preload qb row + vw
    for (int i = tid; i < AA; i += 256) {
        sqb[i] = g_qb[b][i];
        svw[i] = g_vw[i];
    }

    // A: fp32 global -> bf16 fragment-order smem.
    // warp w owns m-tile mt=w. a0:(r,k) a1:(r+8,k) a2:(r,k+8) a3:(r+8,k+8)
    {
        const int r  = row0 + w * 16 + (lane >> 2);
        const int dc = (lane & 3) * 2;
        const float* k0 = key + (size_t)r * DK + dc;
        #pragma unroll 4
        for (int kt = 0; kt < 32; kt++) {
            const float* p = k0 + kt * 16;
            float2 f0 = *(const float2*)(p);
            float2 f1 = *(const float2*)(p + 8 * DK);
            float2 f2 = *(const float2*)(p + 8);
            float2 f3 = *(const float2*)(p + 8 * DK + 8);
            uint4 v;
            v.x = pack_bf16x2(f0.x, f0.y);
            v.y = pack_bf16x2(f1.x, f1.y);
            v.z = pack_bf16x2(f2.x, f2.y);
            v.w = pack_bf16x2(f3.x, f3.y);
            sA[(w * 32 + kt) * 32 + lane] = v;
        }
    }
    __syncthreads();

    float acc[8][4];
    float e0 = 0.f, e1 = 0.f;
    const int cc = (lane & 3) * 2;     // epilogue col offset within n8

    for (int ch = 0; ch < 64; ch++) {
        const int buf = ch & 1;
        if ((ch & 7) == 0) {
            #pragma unroll
            for (int t = 0; t < 8; t++)
                #pragma unroll
                for (int i = 0; i < 4; i++) acc[t][i] = 0.f;
        }
        if (ch + 1 < 64) {
            const char* src = (const char*)g_wkbf + (size_t)(ch + 1) * 8192 + tid * 16;
            uint32_t dst = sb + SOFF_B + (uint32_t)(buf ^ 1) * 8192u + tid * 16;
            cp_async16(dst, src);
            cp_async16(dst + 4096u, src + 4096);
            CP_COMMIT();
            CP_WAIT(1);
        } else {
            CP_WAIT(0);
        }
        __syncthreads();

        const uint2* sB = (const uint2*)(smem + SOFF_B + buf * 8192u);
        #pragma unroll
        for (int kk = 0; kk < 4; kk++) {
            const int kt = (ch & 7) * 4 + kk;
            uint4 av = sA[(w * 32 + kt) * 32 + lane];
            #pragma unroll
            for (int t = 0; t < 8; t++) {
                uint2 bv = sB[(kk * 8 + t) * 32 + lane];
                mma16816(acc[t][0], acc[t][1], acc[t][2], acc[t][3],
                         av.x, av.y, av.z, av.w, bv.x, bv.y);
            }
        }
        __syncthreads();

        if ((ch & 7) == 7) {
            const int nt = ch >> 3;
            const int a_base = nt * 64;
            #pragma unroll
            for (int t = 0; t < 8; t++) {
                int a0 = a_base + t * 8 + cc;
                float q0 = sqb[a0],     q1 = sqb[a0 + 1];
                float w0 = svw[a0],     w1 = svw[a0 + 1];
                e0 += tanhf(acc[t][0] + q0) * w0 + tanhf(acc[t][1] + q1) * w1;
                e1 += tanhf(acc[t][2] + q0) * w0 + tanhf(acc[t][3] + q1) * w1;
            }
        }
    }

    // reduce over the 4 lanes sharing a row (lane%4)
    #pragma unroll
    for (int o = 1; o < 4; o <<= 1) {
        e0 += __shfl_xor_sync(0xffffffffu, e0, o);
        e1 += __shfl_xor_sync(0xffffffffu, e1, o);
    }
    if ((lane & 3) == 0) {
        int r = row0 + w * 16 + (lane >> 2);
        g_e[r]     = e0;
        g_e[r + 8] = e1;
    }
}

// ==================== kernel C: scan -> aw ==================================
__global__ __launch_bounds__(1024) void scan_kernel(
        const float* __restrict__ noise, const float* __restrict__ rp,
        float* __restrict__ aw) {
    const int b = blockIdx.x;
    const int t = threadIdx.x;
    const int lane = t & 31, warp = t >> 5;
    const float rv = rp[0];
    const int base = b * KMAX + t * 4;

    float p[4], l[4];
    #pragma unroll
    for (int j = 0; j < 4; j++) {
        float x = g_e[base + j] + rv + noise[base + j];
        p[j] = 1.0f / (1.0f + expf(-x));
        l[j] = logf(fmaxf(1.0f - p[j], 1e-10f));
    }
    float ex1 = l[0], ex2 = ex1 + l[1], ex3 = ex2 + l[2];
    float tot = ex3 + l[3];

    float s = tot;
    #pragma unroll
    for (int d = 1; d < 32; d <<= 1) {
        float v = __shfl_up_sync(0xffffffffu, s, d);
        if (lane >= d) s += v;
    }
    __shared__ float wsum[32];
    if (lane == 31) wsum[warp] = s;
    __syncthreads();
    if (warp == 0) {
        float w = wsum[lane];
        #pragma unroll
        for (int d = 1; d < 32; d <<= 1) {
            float v = __shfl_up_sync(0xffffffffu, w, d);
            if (lane >= d) w += v;
        }
        wsum[lane] = w;
    }
    __syncthreads();
    float excl = (warp > 0 ? wsum[warp - 1] : 0.f) + (s - tot);
    float bse = 1.0f + excl;
    aw[base + 0] = p[0] * expf(bse);
    aw[base + 1] = p[1] * expf(bse + ex1);
    aw[base + 2] = p[2] * expf(bse + ex2);
    aw[base + 3] = p[3] * expf(bse + ex3);
}

// ==================== kernel D: cv ==========================================
__global__ __launch_bounds__(128) void cv_kernel(
        const float* __restrict__ value, const float* __restrict__ aw,
        float* __restrict__ cv) {
    const int b  = blockIdx.x;
    const int v  = blockIdx.y * 128 + threadIdx.x;
    const int k0 = blockIdx.z * 512;
    const float* vp = value + ((size_t)b * KMAX + k0) * DV + v;
    const float* ap = aw + b * KMAX + k0;
    float acc = 0.f;
    #pragma unroll 8
    for (int k = 0; k < 512; k++)
        acc += __ldg(ap + k) * __ldg(vp + (size_t)k * DV);
    atomicAdd(&cv[b * DV + v], acc);
}

// ==================== launcher ==============================================
extern "C" void kernel_launch(void* const* d_in, const int* in_sizes, int n_in,
                              void* d_out, int out_size) {
    const float* key_enc = (const float*)d_in[0];
    const float* value   = (const float*)d_in[1];
    const float* query   = (const float*)d_in[2];
    const float* noise   = (const float*)d_in[3];
    const float* wk_w    = (const float*)d_in[4];
    const float* wk_b    = (const float*)d_in[5];
    const float* wq_w    = (const float*)d_in[6];
    const float* v_v     = (const float*)d_in[7];
    const float* v_g     = (const float*)d_in[8];
    const float* r       = (const float*)d_in[9];

    float* out = (float*)d_out;
    float* cv  = out;                 // [B, DV]
    float* aw  = out + BB * DV;       // [B, KMAX]

    cudaFuncSetAttribute(gemm_mma_kernel,
                         cudaFuncAttributeMaxDynamicSharedMemorySize, SMEM_GEMM);

    cudaMemsetAsync(cv, 0, BB * DV * sizeof(float), 0);

    vw_kernel<<<1, AA, 0, 0>>>(v_v, v_g);
    qproj_kernel<<<(BB * AA * 32) / 256, 256, 0, 0>>>(query, wq_w, wk_b);
    wkconv_kernel<<<(AA * DK / 2) / 256, 256, 0, 0>>>(wk_w);

    gemm_mma_kernel<<<MM / 128, 256, SMEM_GEMM, 0>>>(key_enc);

    scan_kernel<<<BB, 1024, 0, 0>>>(noise, r, aw);

    dim3 cgrid(BB, DV / 128, KMAX / 512);
    cv_kernel<<<cgrid, 128, 0, 0>>>(value, aw, cv);
}

// round 6
// speedup vs baseline: 1.2980x; 1.2980x over previous
#include <cuda_runtime.h>
#include <cuda_bf16.h>
#include <math.h>
#include <stdint.h>

#define BB 16
#define KMAX 4096
#define DK 512
#define AA 512
#define DV 512
#define MM (BB*KMAX)   // 65536

// ---------------- scratch (device globals) ----------------------------------
__device__ float g_vw[AA];                       // weight-normed v vector
__device__ float g_qb[BB][AA];                   // q projection + wk bias
__device__ float g_e[MM];                        // e_mono
// wk bf16, chunked fragment order:
// [chunk(16)=np*4+kc][ntl(2)][ktl(8)][tp(4)][lane(32)][4 words]
__device__ __align__(16) uint32_t g_wkbf[AA * DK / 2];

// ==================== small helpers =========================================
__device__ __forceinline__ uint32_t smem_u32(const void* p) {
    uint32_t a;
    asm("{ .reg .u64 t; cvta.to.shared.u64 t, %1; cvt.u32.u64 %0, t; }"
        : "=r"(a) : "l"(p));
    return a;
}

__device__ __forceinline__ uint32_t pack_bf16x2(float lo, float hi) {
    __nv_bfloat162 h = __floats2bfloat162_rn(lo, hi);
    return *reinterpret_cast<uint32_t*>(&h);
}

__device__ __forceinline__ void cp_async16(uint32_t dst, const void* src) {
    asm volatile("cp.async.cg.shared.global [%0], [%1], 16;"
                 :: "r"(dst), "l"(src) : "memory");
}
#define CP_COMMIT()  asm volatile("cp.async.commit_group;" ::: "memory")
#define CP_WAIT(N)   asm volatile("cp.async.wait_group %0;" :: "n"(N) : "memory")

__device__ __forceinline__ void mma16816(float* d,
                                         uint32_t a0, uint32_t a1, uint32_t a2, uint32_t a3,
                                         uint32_t b0, uint32_t b1) {
    asm volatile(
        "mma.sync.aligned.m16n8k16.row.col.f32.bf16.bf16.f32 "
        "{%0,%1,%2,%3}, {%4,%5,%6,%7}, {%8,%9}, {%0,%1,%2,%3};"
        : "+f"(d[0]), "+f"(d[1]), "+f"(d[2]), "+f"(d[3])
        : "r"(a0), "r"(a1), "r"(a2), "r"(a3), "r"(b0), "r"(b1));
}

// ==================== kernel A1: v_w ========================================
__global__ void vw_kernel(const float* __restrict__ vv, const float* __restrict__ vg) {
    __shared__ float sh[AA];
    int t = threadIdx.x;
    float x = vv[t];
    sh[t] = x * x;
    __syncthreads();
    for (int s = 256; s > 0; s >>= 1) {
        if (t < s) sh[t] += sh[t + s];
        __syncthreads();
    }
    float nrm = sqrtf(sh[0]);
    g_vw[t] = vg[0] * x / nrm;
}

// ==================== kernel A2: qb[b][a] ===================================
__global__ void qproj_kernel(const float* __restrict__ query,
                             const float* __restrict__ wq,
                             const float* __restrict__ wkb) {
    int gw   = (blockIdx.x * blockDim.x + threadIdx.x) >> 5;
    int lane = threadIdx.x & 31;
    if (gw >= BB * AA) return;
    int b = gw >> 9;
    int a = gw & 511;
    const float* qp = query + (size_t)b * DK;
    const float* wp = wq + (size_t)a * DK;
    float s = 0.f;
    #pragma unroll 4
    for (int d = lane; d < DK; d += 32) s += qp[d] * wp[d];
    #pragma unroll
    for (int o = 16; o > 0; o >>= 1) s += __shfl_down_sync(0xffffffffu, s, o);
    if (lane == 0) g_qb[b][a] = s + wkb[a];
}

// ==================== kernel A3: wk -> bf16 chunked fragment order ==========
// B frag m16n8k16 col: reg0 = {B[k0][n],B[k0+1][n]}, reg1 = same k+8,
// k0=(lane%4)*2, n=lane/4. Words per (tp,lane): [t_even.b0, t_even.b1,
// t_odd.b0, t_odd.b1].
__global__ __launch_bounds__(256) void wkconv_kernel(const float* __restrict__ wk) {
    int idx = blockIdx.x * 256 + threadIdx.x;      // one b32 word each (131072)
    int a  = idx >> 8;                             // n: 0..511
    int d  = (idx & 255) * 2;                      // k: even
    float2 f = *(const float2*)(wk + (size_t)a * DK + d);
    int nt  = a >> 6;
    int np  = nt >> 1;
    int ntl = nt & 1;
    int t   = (a >> 3) & 7;
    int tp  = t >> 1;
    int th  = t & 1;
    int ktg = d >> 4;                              // global k16 tile 0..31
    int kc  = ktg >> 3;
    int ktl = ktg & 7;
    int lane = (a & 7) * 4 + ((d & 7) >> 1);
    int j   = (d & 15) >> 3;
    uint32_t off = (uint32_t)(np * 4 + kc) * 8192u
                 + ((((ntl * 8 + ktl) * 4 + tp) * 32) + lane) * 4u
                 + th * 2 + j;
    g_wkbf[off] = pack_bf16x2(f.x, f.y);
}

// ==================== kernel B: mma.sync bf16 GEMM + fused epilogue =========
// CTA: 128 rows x 512 cols x K=512. Warp = m32 x n64 (mg = w&3, ntl = w>>2).
// B streamed in 32KB chunks (2 n-tiles x 128 k), double buffered.
#define SOFF_QB   0u
#define SOFF_VW   2048u
#define SOFF_RED  4096u                  // 256 floats
#define SOFF_A    5120u                  // 8 mt * 32 kt * 32 lane * 16B = 131072
#define SOFF_B    136192u                // 2 x 32768
#define SMEM_GEMM (SOFF_B + 2u*32768u)   // 201728

__global__ __launch_bounds__(256, 1) void gemm_mma_kernel(
        const float* __restrict__ key) {
    extern __shared__ char smem[];
    const uint32_t sb = smem_u32(smem);
    float* sqb = (float*)(smem + SOFF_QB);
    float* svw = (float*)(smem + SOFF_VW);
    float* red = (float*)(smem + SOFF_RED);
    uint4* sA  = (uint4*)(smem + SOFF_A);

    const int tid  = threadIdx.x;
    const int w    = tid >> 5;
    const int lane = tid & 31;
    const int row0 = blockIdx.x * 128;
    const int b    = blockIdx.x >> 5;

    // prefetch B chunk 0 (32KB contiguous)
    {
        const char* src = (const char*)g_wkbf + (size_t)tid * 16;
        uint32_t dst = sb + SOFF_B + tid * 16;
        #pragma unroll
        for (int i = 0; i < 8; i++)
            cp_async16(dst + i * 4096u, src + i * 4096);
        CP_COMMIT();
    }

    for (int i = tid; i < AA; i += 256) {
        sqb[i] = g_qb[b][i];
        svw[i] = g_vw[i];
    }

    // A: fp32 global -> bf16 fragment-order smem. warp w owns m-tile mt=w.
    {
        const int r  = row0 + w * 16 + (lane >> 2);
        const int dc = (lane & 3) * 2;
        const float* k0 = key + (size_t)r * DK + dc;
        #pragma unroll 4
        for (int kt = 0; kt < 32; kt++) {
            const float* p = k0 + kt * 16;
            float2 f0 = *(const float2*)(p);
            float2 f1 = *(const float2*)(p + 8 * DK);
            float2 f2 = *(const float2*)(p + 8);
            float2 f3 = *(const float2*)(p + 8 * DK + 8);
            uint4 v;
            v.x = pack_bf16x2(f0.x, f0.y);
            v.y = pack_bf16x2(f1.x, f1.y);
            v.z = pack_bf16x2(f2.x, f2.y);
            v.w = pack_bf16x2(f3.x, f3.y);
            sA[(w * 32 + kt) * 32 + lane] = v;
        }
    }
    __syncthreads();

    const int mg  = w & 3;
    const int ntl = w >> 2;
    const int cc  = (lane & 3) * 2;

    float e00 = 0.f, e01 = 0.f, e10 = 0.f, e11 = 0.f;

    for (int np = 0; np < 4; np++) {
        float acc[2][8][4];
        #pragma unroll
        for (int m = 0; m < 2; m++)
            #pragma unroll
            for (int t = 0; t < 8; t++)
                #pragma unroll
                for (int i = 0; i < 4; i++) acc[m][t][i] = 0.f;

        for (int kc = 0; kc < 4; kc++) {
            const int cid = np * 4 + kc;
            const int buf = cid & 1;
            if (cid + 1 < 16) {
                const char* src = (const char*)g_wkbf + (size_t)(cid + 1) * 32768 + tid * 16;
                uint32_t dst = sb + SOFF_B + (uint32_t)(buf ^ 1) * 32768u + tid * 16;
                #pragma unroll
                for (int i = 0; i < 8; i++)
                    cp_async16(dst + i * 4096u, src + i * 4096);
                CP_COMMIT();
                CP_WAIT(1);
            } else {
                CP_WAIT(0);
            }
            __syncthreads();

            const uint4* sBc = (const uint4*)(smem + SOFF_B + buf * 32768u)
                             + (uint32_t)ntl * 8 * 4 * 32;
            #pragma unroll
            for (int ktl = 0; ktl < 8; ktl++) {
                const int kt = kc * 8 + ktl;
                uint4 av0 = sA[((mg * 2 + 0) * 32 + kt) * 32 + lane];
                uint4 av1 = sA[((mg * 2 + 1) * 32 + kt) * 32 + lane];
                #pragma unroll
                for (int tp = 0; tp < 4; tp++) {
                    uint4 bv = sBc[(ktl * 4 + tp) * 32 + lane];
                    mma16816(acc[0][tp * 2],     av0.x, av0.y, av0.z, av0.w, bv.x, bv.y);
                    mma16816(acc[0][tp * 2 + 1], av0.x, av0.y, av0.z, av0.w, bv.z, bv.w);
                    mma16816(acc[1][tp * 2],     av1.x, av1.y, av1.z, av1.w, bv.x, bv.y);
                    mma16816(acc[1][tp * 2 + 1], av1.x, av1.y, av1.z, av1.w, bv.z, bv.w);
                }
            }
            __syncthreads();
        }

        // epilogue for this 128-col block
        const int colbase = np * 128 + ntl * 64;
        #pragma unroll
        for (int t = 0; t < 8; t++) {
            int a0 = colbase + t * 8 + cc;
            float q0 = sqb[a0],     q1 = sqb[a0 + 1];
            float w0 = svw[a0],     w1 = svw[a0 + 1];
            e00 += tanhf(acc[0][t][0] + q0) * w0 + tanhf(acc[0][t][1] + q1) * w1;
            e01 += tanhf(acc[0][t][2] + q0) * w0 + tanhf(acc[0][t][3] + q1) * w1;
            e10 += tanhf(acc[1][t][0] + q0) * w0 + tanhf(acc[1][t][1] + q1) * w1;
            e11 += tanhf(acc[1][t][2] + q0) * w0 + tanhf(acc[1][t][3] + q1) * w1;
        }
    }

    // reduce over the 4 lanes sharing each row
    #pragma unroll
    for (int o = 1; o < 4; o <<= 1) {
        e00 += __shfl_xor_sync(0xffffffffu, e00, o);
        e01 += __shfl_xor_sync(0xffffffffu, e01, o);
        e10 += __shfl_xor_sync(0xffffffffu, e10, o);
        e11 += __shfl_xor_sync(0xffffffffu, e11, o);
    }
    if ((lane & 3) == 0) {
        int rb = mg * 32 + (lane >> 2);
        red[ntl * 128 + rb +  0] = e00;
        red[ntl * 128 + rb +  8] = e01;
        red[ntl * 128 + rb + 16] = e10;
        red[ntl * 128 + rb + 24] = e11;
    }
    __syncthreads();
    if (tid < 128) g_e[row0 + tid] = red[tid] + red[128 + tid];
}

// ==================== kernel C: scan -> aw ==================================
__global__ __launch_bounds__(1024) void scan_kernel(
        const float* __restrict__ noise, const float* __restrict__ rp,
        float* __restrict__ aw) {
    const int b = blockIdx.x;
    const int t = threadIdx.x;
    const int lane = t & 31, warp = t >> 5;
    const float rv = rp[0];
    const int base = b * KMAX + t * 4;

    float p[4], l[4];
    #pragma unroll
    for (int j = 0; j < 4; j++) {
        float x = g_e[base + j] + rv + noise[base + j];
        p[j] = 1.0f / (1.0f + expf(-x));
        l[j] = logf(fmaxf(1.0f - p[j], 1e-10f));
    }
    float ex1 = l[0], ex2 = ex1 + l[1], ex3 = ex2 + l[2];
    float tot = ex3 + l[3];

    float s = tot;
    #pragma unroll
    for (int d = 1; d < 32; d <<= 1) {
        float v = __shfl_up_sync(0xffffffffu, s, d);
        if (lane >= d) s += v;
    }
    __shared__ float wsum[32];
    if (lane == 31) wsum[warp] = s;
    __syncthreads();
    if (warp == 0) {
        float w = wsum[lane];
        #pragma unroll
        for (int d = 1; d < 32; d <<= 1) {
            float v = __shfl_up_sync(0xffffffffu, w, d);
            if (lane >= d) w += v;
        }
        wsum[lane] = w;
    }
    __syncthreads();
    float excl = (warp > 0 ? wsum[warp - 1] : 0.f) + (s - tot);
    float bse = 1.0f + excl;
    aw[base + 0] = p[0] * expf(bse);
    aw[base + 1] = p[1] * expf(bse + ex1);
    aw[base + 2] = p[2] * expf(bse + ex2);
    aw[base + 3] = p[3] * expf(bse + ex3);
}

// ==================== kernel D: cv (float4, k-split 32) =====================
__global__ __launch_bounds__(128) void cv_kernel(
        const float* __restrict__ value, const float* __restrict__ aw,
        float* __restrict__ cv) {
    const int b  = blockIdx.x;
    const int k0 = blockIdx.z * 128;
    const float4* vp = (const float4*)(value + ((size_t)b * KMAX + k0) * DV)
                     + threadIdx.x;
    const float* ap = aw + b * KMAX + k0;
    float4 acc = make_float4(0.f, 0.f, 0.f, 0.f);
    #pragma unroll 8
    for (int k = 0; k < 128; k++) {
        float a = __ldg(ap + k);
        float4 v = __ldg(vp + (size_t)k * (DV / 4));
        acc.x += a * v.x;
        acc.y += a * v.y;
        acc.z += a * v.z;
        acc.w += a * v.w;
    }
    float* dst = cv + b * DV + threadIdx.x * 4;
    atomicAdd(dst + 0, acc.x);
    atomicAdd(dst + 1, acc.y);
    atomicAdd(dst + 2, acc.z);
    atomicAdd(dst + 3, acc.w);
}

// ==================== launcher ==============================================
extern "C" void kernel_launch(void* const* d_in, const int* in_sizes, int n_in,
                              void* d_out, int out_size) {
    const float* key_enc = (const float*)d_in[0];
    const float* value   = (const float*)d_in[1];
    const float* query   = (const float*)d_in[2];
    const float* noise   = (const float*)d_in[3];
    const float* wk_w    = (const float*)d_in[4];
    const float* wk_b    = (const float*)d_in[5];
    const float* wq_w    = (const float*)d_in[6];
    const float* v_v     = (const float*)d_in[7];
    const float* v_g     = (const float*)d_in[8];
    const float* r       = (const float*)d_in[9];

    float* out = (float*)d_out;
    float* cv  = out;                 // [B, DV]
    float* aw  = out + BB * DV;       // [B, KMAX]

    cudaFuncSetAttribute(gemm_mma_kernel,
                         cudaFuncAttributeMaxDynamicSharedMemorySize, SMEM_GEMM);

    cudaMemsetAsync(cv, 0, BB * DV * sizeof(float), 0);

    vw_kernel<<<1, AA, 0, 0>>>(v_v, v_g);
    qproj_kernel<<<(BB * AA * 32) / 256, 256, 0, 0>>>(query, wq_w, wk_b);
    wkconv_kernel<<<(AA * DK / 2) / 256, 256, 0, 0>>>(wk_w);

    gemm_mma_kernel<<<MM / 128, 256, SMEM_GEMM, 0>>>(key_enc);

    scan_kernel<<<BB, 1024, 0, 0>>>(noise, r, aw);

    dim3 cgrid(BB, 1, KMAX / 128);
    cv_kernel<<<cgrid, 128, 0, 0>>>(value, aw, cv);
}